// round 16
// baseline (speedup 1.0000x reference)
#include <cuda_runtime.h>
#include <cuda_fp16.h>
#include <math.h>
#include <stdint.h>

#define D_MODEL 1024
#define D_FF    4096
#define NE      8
#define NT      8192
#define ROWS_MAX 18432          // 16384 + 8*256 padding (256-aligned segments)
#define NTILES_M 72             // ROWS_MAX/256 m-tiles

// ---------------- static scratch (no runtime allocation allowed) ----------------
__device__ int    g_topk_idx[NT * 2];
__device__ float  g_topk_prob[NT * 2];
__device__ int    g_pos[NT * 2];
__device__ int    g_counts[NE];
__device__ float  g_probs_sum[NE];
__device__ int    g_poff[NE + 1];
__device__ int    g_cursor[NE];
__device__ __half g_xa[(size_t)ROWS_MAX * D_MODEL];       // permuted fp16 x
__device__ __half g_w1h[(size_t)NE * D_FF * D_MODEL];     // w1^T [e][f][k] fp16
__device__ __half g_w2h[(size_t)NE * D_MODEL * D_FF];     // w2^T [e][d][k] fp16
__device__ __half g_h[(size_t)ROWS_MAX * D_FF];           // GEMM1 out fp16
__device__ float  g_y[(size_t)ROWS_MAX * D_MODEL];        // GEMM2 out fp32

// ---------------- PTX helpers (arch-portable only) ----------------
__device__ __forceinline__ uint32_t smem_to_u32(const void* p) {
    uint32_t a;
    asm("{ .reg .u64 t; cvta.to.shared.u64 t, %1; cvt.u32.u64 %0, t; }" : "=r"(a) : "l"(p));
    return a;
}
__device__ __forceinline__ void cp16(uint32_t s, const void* g) {
    asm volatile("cp.async.cg.shared.global [%0], [%1], 16;\n" :: "r"(s), "l"(g) : "memory");
}
#define CP_COMMIT() asm volatile("cp.async.commit_group;\n" ::: "memory")
#define CP_WAIT(n)  asm volatile("cp.async.wait_group %0;\n" :: "n"(n) : "memory")

// fp16 mma, fp32 accumulate (same 11-bit mantissa as tf32; R5/R13-validated)
__device__ __forceinline__ void mma_f16(float* c, const unsigned* a, const unsigned* b) {
    asm volatile(
        "mma.sync.aligned.m16n8k16.row.col.f32.f16.f16.f32 "
        "{%0,%1,%2,%3},{%4,%5,%6,%7},{%8,%9},{%0,%1,%2,%3};"
        : "+f"(c[0]), "+f"(c[1]), "+f"(c[2]), "+f"(c[3])
        : "r"(a[0]), "r"(a[1]), "r"(a[2]), "r"(a[3]), "r"(b[0]), "r"(b[1]));
}

// ---------------- init ----------------
__global__ void k_init() {
    int i = threadIdx.x;
    if (i < NE) { g_counts[i] = 0; g_probs_sum[i] = 0.f; g_cursor[i] = 0; }
}

// ---------------- router: 1 warp per token ----------------
__global__ void __launch_bounds__(256) k_router(const float* __restrict__ x,
                                                const float* __restrict__ gw,
                                                const float* __restrict__ gb) {
    __shared__ float gws[NE * D_MODEL];
    __shared__ float psum[NE];
    __shared__ int   scnt[NE];
    int tid = threadIdx.x;
    for (int i = tid; i < NE * D_MODEL; i += 256) {
        int d = i >> 3, e = i & 7;
        gws[e * D_MODEL + d] = gw[i];
    }
    if (tid < NE) { psum[tid] = 0.f; scnt[tid] = 0; }
    __syncthreads();

    int lane = tid & 31, warp = tid >> 5;
    int t = blockIdx.x * 8 + warp;
    const float* xr = x + (size_t)t * D_MODEL;

    float acc[NE];
#pragma unroll
    for (int e = 0; e < NE; e++) acc[e] = 0.f;
    for (int i = 0; i < D_MODEL / 32; i++) {
        int d = i * 32 + lane;
        float xv = xr[d];
#pragma unroll
        for (int e = 0; e < NE; e++) acc[e] += xv * gws[e * D_MODEL + d];
    }
#pragma unroll
    for (int e = 0; e < NE; e++)
        for (int off = 16; off > 0; off >>= 1)
            acc[e] += __shfl_xor_sync(0xffffffffu, acc[e], off);

    if (lane == 0) {
        float l[NE], p[NE];
        float m = -1e30f;
#pragma unroll
        for (int e = 0; e < NE; e++) { l[e] = acc[e] + gb[e]; m = fmaxf(m, l[e]); }
        float s = 0.f;
#pragma unroll
        for (int e = 0; e < NE; e++) { p[e] = expf(l[e] - m); s += p[e]; }
        float inv = 1.f / s;
#pragma unroll
        for (int e = 0; e < NE; e++) { p[e] *= inv; atomicAdd(&psum[e], p[e]); }
        int e1 = 0;
#pragma unroll
        for (int e = 1; e < NE; e++) if (p[e] > p[e1]) e1 = e;
        int e2 = -1;
#pragma unroll
        for (int e = 0; e < NE; e++) {
            if (e == e1) continue;
            if (e2 < 0 || p[e] > p[e2]) e2 = e;
        }
        float pr = 1.f / (p[e1] + p[e2]);
        g_topk_idx[2 * t] = e1;     g_topk_idx[2 * t + 1] = e2;
        g_topk_prob[2 * t] = p[e1] * pr; g_topk_prob[2 * t + 1] = p[e2] * pr;
        atomicAdd(&scnt[e1], 1);
        atomicAdd(&scnt[e2], 1);
    }
    __syncthreads();
    if (tid < NE) {
        atomicAdd(&g_probs_sum[tid], psum[tid]);
        atomicAdd(&g_counts[tid], scnt[tid]);
    }
}

// ---------------- stats + 256-aligned segment offsets ----------------
__global__ void k_stats(float* __restrict__ out) {
    if (threadIdx.x == 0) {
        int off = 0;
        for (int e = 0; e < NE; e++) {
            g_poff[e] = off;
            off += ((g_counts[e] + 255) >> 8) << 8;   // 256-aligned (M-tile = 256)
        }
        g_poff[NE] = off;
        float* tail = out + (size_t)NT * D_MODEL;
        for (int e = 0; e < NE; e++) tail[e] = (float)g_counts[e] / (float)(NT * 2);
        float avg[NE], mean = 0.f;
        for (int e = 0; e < NE; e++) { avg[e] = g_probs_sum[e] / (float)NT; mean += avg[e]; }
        mean /= (float)NE;
        float var = 0.f;
        for (int e = 0; e < NE; e++) { float d = avg[e] - mean; var += d * d; }
        tail[NE] = var / (float)(NE - 1);   // ddof=1
    }
}

// ---------------- pack (fused scatter): claim slot, gather + fp16-convert row --
__global__ void __launch_bounds__(256) k_pack(const float* __restrict__ x) {
    __shared__ int s_p;
    int s = blockIdx.x;
    int tok = s >> 1;
    if (threadIdx.x == 0) {
        int e = g_topk_idx[s];
        int p = g_poff[e] + atomicAdd(&g_cursor[e], 1);
        g_pos[s] = p;
        s_p = p;
    }
    __syncthreads();
    int p = s_p;
    int i = threadIdx.x;
    float4 v = *(const float4*)&x[(size_t)tok * D_MODEL + i * 4];
    __half2* d = (__half2*)&g_xa[(size_t)p * D_MODEL + i * 4];
    d[0] = __floats2half2_rn(v.x, v.y);
    d[1] = __floats2half2_rn(v.z, v.w);
}

// ---------------- weight transpose to K-major fp16 -----------------
template <int R, int C>
__global__ void __launch_bounds__(256) k_transpose(const float* __restrict__ src,
                                                   __half* __restrict__ dst) {
    __shared__ float t[32][33];
    int e = blockIdx.z;
    const float* s = src + (size_t)e * R * C;
    __half* d = dst + (size_t)e * R * C;
    int c0 = blockIdx.x * 32, r0 = blockIdx.y * 32;
#pragma unroll
    for (int j = 0; j < 32; j += 8)
        t[threadIdx.y + j][threadIdx.x] =
            s[(size_t)(r0 + threadIdx.y + j) * C + c0 + threadIdx.x];
    __syncthreads();
#pragma unroll
    for (int j = 0; j < 32; j += 8)
        d[(size_t)(c0 + threadIdx.y + j) * R + r0 + threadIdx.x] =
            __float2half_rn(t[threadIdx.x][threadIdx.y + j]);
}

// ---------------- fp16 GEMM: 256x128 CTA tile, 8 warps of 64x64, k64 chunks ----
// A stage: 256 rows x 72 halves = 36864B; B stage: 128 n-rows x 72 halves = 18432B
// One CTA/SM (occ 1, 256 regs/thread budget); STS traffic/kt cut 72->54 KB/SM
#define A_ST_BYTES 36864
#define B_ST_BYTES 18432
#define ST_BYTES (A_ST_BYTES + B_ST_BYTES)     // 55296 per stage
#define SMEM_GEMM (3 * ST_BYTES)               // 165888 bytes

__device__ __forceinline__ void fill_stage(uint32_t aS, uint32_t bS,
                                           const __half* __restrict__ A0,
                                           const __half* __restrict__ B0,
                                           int koff, int kdim, int tid) {
#pragma unroll
    for (int i = 0; i < 8; i++) {          // A: 2048 cp16 (256 rows x 8 chunks)
        int id = tid + i * 256;
        int row = id >> 3, ch = id & 7;
        cp16(aS + (uint32_t)(row * 144 + ch * 16),
             A0 + (size_t)row * kdim + koff + ch * 8);
    }
#pragma unroll
    for (int i = 0; i < 4; i++) {          // B: 1024 cp16 (128 n-rows x 8 chunks)
        int id = tid + i * 256;
        int row = id >> 3, ch = id & 7;
        cp16(bS + (uint32_t)(row * 144 + ch * 16),
             B0 + (size_t)row * kdim + koff + ch * 8);
    }
}

template <int KDIM, int NDIM, bool FIRST>
__global__ void __launch_bounds__(256, 1) k_gemm(const __half* __restrict__ Bg,
                                                 const float* __restrict__ bias) {
    extern __shared__ char smc[];
    const int row0 = blockIdx.x * 256;
    if (row0 >= g_poff[NE]) return;
    int e = 0;
#pragma unroll
    for (int i = 1; i < NE; i++) if (row0 >= g_poff[i]) e = i;
    const int n0 = blockIdx.y * 128;
    const int tid = threadIdx.x, lane = tid & 31, warp = tid >> 5;
    const int wm = warp & 3, wn = warp >> 2;          // 4x2 grid of 64x64 warp tiles
    const int gid = lane >> 2, ktid = lane & 3;
    const uint32_t sb = smem_to_u32(smc);

    // resolve device symbols IN DEVICE CODE
    const __half* A0 = (FIRST ? g_xa : g_h) + (size_t)row0 * KDIM;
    const __half* B0 = Bg + (size_t)e * KDIM * NDIM + (size_t)n0 * KDIM;
    const int NKT = KDIM / 64;

    // prologue: 2 stages in flight
    fill_stage(sb, sb + A_ST_BYTES, A0, B0, 0, KDIM, tid);
    CP_COMMIT();
    fill_stage(sb + ST_BYTES, sb + ST_BYTES + A_ST_BYTES, A0, B0, 64, KDIM, tid);
    CP_COMMIT();

    float acc[4][8][4];
#pragma unroll
    for (int a = 0; a < 4; a++)
#pragma unroll
        for (int b = 0; b < 8; b++)
#pragma unroll
            for (int c = 0; c < 4; c++) acc[a][b][c] = 0.f;

    // per-thread fragment base offsets (words)
    const int aBase0 = (wm * 64 + gid) * 36 + ktid;   // + mt*16*36 + kkw(+4)
    const int bBase0 = (wn * 64 + gid) * 36 + ktid;   // + nt*8*36  + kkw(+4)

#pragma unroll 1
    for (int kt = 0; kt < NKT; kt++) {
        CP_WAIT(1);
        __syncthreads();
        const int cn = kt + 2;
        if (cn < NKT) {
            const uint32_t s2 = sb + (uint32_t)(cn % 3) * ST_BYTES;
            fill_stage(s2, s2 + A_ST_BYTES, A0, B0, cn * 64, KDIM, tid);
        }
        CP_COMMIT();
        const uint32_t* Aw = (const uint32_t*)(smc + (kt % 3) * ST_BYTES);
        const uint32_t* Bw = Aw + A_ST_BYTES / 4;     // 9216 words

#pragma unroll
        for (int kk = 0; kk < 4; kk++) {              // 4 x k16
            const int kkw = kk * 8;
            unsigned a[4][4], b[8][2];
#pragma unroll
            for (int mt = 0; mt < 4; mt++) {
                int base = aBase0 + mt * (16 * 36) + kkw;
                a[mt][0] = Aw[base];
                a[mt][1] = Aw[base + 8 * 36];
                a[mt][2] = Aw[base + 4];
                a[mt][3] = Aw[base + 8 * 36 + 4];
            }
#pragma unroll
            for (int nt = 0; nt < 8; nt++) {
                int base = bBase0 + nt * (8 * 36) + kkw;
                b[nt][0] = Bw[base];
                b[nt][1] = Bw[base + 4];
            }
#pragma unroll
            for (int mt = 0; mt < 4; mt++)
#pragma unroll
                for (int nt = 0; nt < 8; nt++)
                    mma_f16(acc[mt][nt], a[mt], b[nt]);
        }
    }

    // epilogue
#pragma unroll
    for (int mt = 0; mt < 4; mt++) {
        int rr0 = row0 + wm * 64 + mt * 16 + gid;
        int rr1 = rr0 + 8;
#pragma unroll
        for (int nt = 0; nt < 8; nt++) {
            int c = n0 + wn * 64 + nt * 8 + ktid * 2;
            float* a = acc[mt][nt];
            if (FIRST) {
                float bb0 = bias[e * NDIM + c];
                float bb1 = bias[e * NDIM + c + 1];
                __half2 h0 = __floats2half2_rn(fmaxf(a[0] + bb0, 0.f),
                                               fmaxf(a[1] + bb1, 0.f));
                __half2 h1 = __floats2half2_rn(fmaxf(a[2] + bb0, 0.f),
                                               fmaxf(a[3] + bb1, 0.f));
                *(__half2*)&g_h[(size_t)rr0 * D_FF + c] = h0;
                *(__half2*)&g_h[(size_t)rr1 * D_FF + c] = h1;
            } else {
                *(float2*)&g_y[(size_t)rr0 * D_MODEL + c] = make_float2(a[0], a[1]);
                *(float2*)&g_y[(size_t)rr1 * D_MODEL + c] = make_float2(a[2], a[3]);
            }
        }
    }
}

// ---------------- combine ----------------
__global__ void __launch_bounds__(256) k_combine(const float* __restrict__ b2,
                                                 float* __restrict__ out) {
    int t = blockIdx.x, i = threadIdx.x;
    int e0 = g_topk_idx[2 * t], e1 = g_topk_idx[2 * t + 1];
    float p0 = g_topk_prob[2 * t], p1 = g_topk_prob[2 * t + 1];
    int q0 = g_pos[2 * t], q1 = g_pos[2 * t + 1];
    float4 y0 = *(const float4*)&g_y[(size_t)q0 * D_MODEL + i * 4];
    float4 y1 = *(const float4*)&g_y[(size_t)q1 * D_MODEL + i * 4];
    float4 c0 = *(const float4*)&b2[(size_t)e0 * D_MODEL + i * 4];
    float4 c1 = *(const float4*)&b2[(size_t)e1 * D_MODEL + i * 4];
    float4 o;
    o.x = p0 * (y0.x + c0.x) + p1 * (y1.x + c1.x);
    o.y = p0 * (y0.y + c0.y) + p1 * (y1.y + c1.y);
    o.z = p0 * (y0.z + c0.z) + p1 * (y1.z + c1.z);
    o.w = p0 * (y0.w + c0.w) + p1 * (y1.w + c1.w);
    *(float4*)&out[(size_t)t * D_MODEL + i * 4] = o;
}

// ---------------- launch ----------------
extern "C" void kernel_launch(void* const* d_in, const int* in_sizes, int n_in,
                              void* d_out, int out_size) {
    (void)in_sizes; (void)n_in; (void)out_size;
    const float* x  = (const float*)d_in[0];
    const float* gw = (const float*)d_in[1];
    const float* gb = (const float*)d_in[2];
    const float* w1 = (const float*)d_in[3];
    const float* b1 = (const float*)d_in[4];
    const float* w2 = (const float*)d_in[5];
    const float* b2 = (const float*)d_in[6];
    float* out = (float*)d_out;

    static int attr_done = 0;
    if (!attr_done) {
        cudaFuncSetAttribute(k_gemm<D_MODEL, D_FF, true>,
                             cudaFuncAttributeMaxDynamicSharedMemorySize, SMEM_GEMM);
        cudaFuncSetAttribute(k_gemm<D_FF, D_MODEL, false>,
                             cudaFuncAttributeMaxDynamicSharedMemorySize, SMEM_GEMM);
        attr_done = 1;
    }

    __half* w1h; cudaGetSymbolAddress((void**)&w1h, g_w1h);
    __half* w2h; cudaGetSymbolAddress((void**)&w2h, g_w2h);

    k_init<<<1, 32>>>();
    k_router<<<NT / 8, 256>>>(x, gw, gb);
    k_stats<<<1, 32>>>(out);
    k_pack<<<NT * 2, 256>>>(x);
    k_transpose<D_MODEL, D_FF><<<dim3(D_FF / 32, D_MODEL / 32, NE), dim3(32, 8)>>>(w1, w1h);
    k_transpose<D_FF, D_MODEL><<<dim3(D_MODEL / 32, D_FF / 32, NE), dim3(32, 8)>>>(w2, w2h);
    k_gemm<D_MODEL, D_FF, true ><<<dim3(NTILES_M, D_FF / 128), 256, SMEM_GEMM>>>(w1h, b1);
    k_gemm<D_FF, D_MODEL, false><<<dim3(NTILES_M, D_MODEL / 128), 256, SMEM_GEMM>>>(w2h, (const float*)0);
    k_combine<<<NT, 256>>>(b2, out);
}